// round 6
// baseline (speedup 1.0000x reference)
#include <cuda_runtime.h>
#include <cuda_bf16.h>
#include <math.h>

// ---- constants ----
#define TT   2048
#define DM   1024
#define NH   16
#define HD   64
#define NBLK 32
#define NSEL 16

// ---- static scratch ----
__device__ float g_q   [TT * DM];
__device__ float g_k   [TT * HD];
__device__ float g_v   [TT * HD];
__device__ float g_gate[TT * 48];
__device__ float g_kc  [NBLK * HD];
__device__ float g_vc  [NBLK * HD];
__device__ float g_ocmp[TT * DM];
__device__ float g_o   [TT * DM];
__device__ int   g_sel [TT * NSEL];

// ======================================================================
// GEMM: C[M,N] = A[M,1024] * B[N,1024]^T.  BM=128 BN=64 BK=16, 256 thr.
// ======================================================================
__device__ __forceinline__ void gemm_body(const float* __restrict__ A,
                                          const float* __restrict__ B,
                                          float* __restrict__ C, int N)
{
    __shared__ float As[16][132];
    __shared__ float Bs[16][68];
    const int K = 1024;
    int tid = threadIdx.x;
    int tr = tid >> 4, tc = tid & 15;
    int row0 = blockIdx.y * 128, col0 = blockIdx.x * 64;
    float acc[8][4];
#pragma unroll
    for (int i = 0; i < 8; i++)
#pragma unroll
        for (int j = 0; j < 4; j++) acc[i][j] = 0.f;

    int ar = tid >> 2, aq = tid & 3;

    for (int kt = 0; kt < K; kt += 16) {
#pragma unroll
        for (int i = 0; i < 2; i++) {
            int r = ar + i * 64;
            float4 va = *(const float4*)(A + (size_t)(row0 + r) * K + kt + aq * 4);
            As[aq*4+0][r] = va.x; As[aq*4+1][r] = va.y;
            As[aq*4+2][r] = va.z; As[aq*4+3][r] = va.w;
        }
        {
            float4 vb = make_float4(0.f,0.f,0.f,0.f);
            if (col0 + ar < N)
                vb = *(const float4*)(B + (size_t)(col0 + ar) * K + kt + aq * 4);
            Bs[aq*4+0][ar] = vb.x; Bs[aq*4+1][ar] = vb.y;
            Bs[aq*4+2][ar] = vb.z; Bs[aq*4+3][ar] = vb.w;
        }
        __syncthreads();
#pragma unroll
        for (int k = 0; k < 16; k++) {
            float4 a0 = *(const float4*)(&As[k][tr*8]);
            float4 a1 = *(const float4*)(&As[k][tr*8+4]);
            float4 b  = *(const float4*)(&Bs[k][tc*4]);
            float av[8] = {a0.x,a0.y,a0.z,a0.w,a1.x,a1.y,a1.z,a1.w};
            float bv[4] = {b.x,b.y,b.z,b.w};
#pragma unroll
            for (int i = 0; i < 8; i++)
#pragma unroll
                for (int j = 0; j < 4; j++) acc[i][j] += av[i] * bv[j];
        }
        __syncthreads();
    }
    if (col0 + tc*4 < N) {
#pragma unroll
        for (int i = 0; i < 8; i++) {
            float4 o = make_float4(acc[i][0], acc[i][1], acc[i][2], acc[i][3]);
            *(float4*)(C + (size_t)(row0 + tr*8 + i) * N + col0 + tc*4) = o;
        }
    }
}

__global__ __launch_bounds__(256) void proj_gemm_kernel(
    const float* __restrict__ x,
    const float* __restrict__ Wq, const float* __restrict__ Wk,
    const float* __restrict__ Wv, const float* __restrict__ Wg)
{
    const float* B; float* C; int N;
    if      (blockIdx.z == 0) { B = Wq; C = g_q;    N = 1024; }
    else if (blockIdx.z == 1) { B = Wk; C = g_k;    N = 64;   }
    else if (blockIdx.z == 2) { B = Wv; C = g_v;    N = 64;   }
    else                      { B = Wg; C = g_gate; N = 48;   }
    if ((int)blockIdx.x * 64 >= N) return;
    gemm_body(x, B, C, N);
}

__global__ __launch_bounds__(256) void out_gemm_kernel(
    const float* __restrict__ Wo, float* __restrict__ out)
{
    gemm_body(g_o, Wo, out, 1024);
}

// ======================================================================
// Block mean pool
// ======================================================================
__global__ void pool_kernel()
{
    int b = blockIdx.x, d = threadIdx.x;
    float sk = 0.f, sv = 0.f;
    for (int j = 0; j < 64; j++) {
        sk += g_k[(b*64 + j)*64 + d];
        sv += g_v[(b*64 + j)*64 + d];
    }
    g_kc[b*64 + d] = sk * (1.f/64.f);
    g_vc[b*64 + d] = sv * (1.f/64.f);
}

// ======================================================================
// Compressed attention + top-k selection. CTA/token, 256 thr (8 warps,
// 2 heads each).
// ======================================================================
__global__ __launch_bounds__(256) void cmp_attn_kernel()
{
    int t = blockIdx.x;
    int tid = threadIdx.x, lane = tid & 31, w = tid >> 5;
    __shared__ float sKC[32*65], sVC[32*65];
    __shared__ float sP[16*36];
    __shared__ float simp[32];

    for (int i = tid; i < 2048; i += 256) {
        int c = i >> 6, d = i & 63;
        sKC[c*65 + d] = g_kc[i];
        sVC[c*65 + d] = g_vc[i];
    }
    __syncthreads();

    int nv = (t + 1) >> 6;            // fully-past blocks
    int h0 = w*2, h1 = w*2 + 1;
    size_t qb = (size_t)t * 1024;
    float q00 = g_q[qb + h0*64 + lane],      q01 = g_q[qb + h0*64 + 32 + lane];
    float q10 = g_q[qb + h1*64 + lane],      q11 = g_q[qb + h1*64 + 32 + lane];

    for (int c = 0; c < nv; c++) {
        float k0 = sKC[c*65 + lane], k1 = sKC[c*65 + 32 + lane];
        float a = q00*k0 + q01*k1;
        float b = q10*k0 + q11*k1;
        for (int o = 16; o; o >>= 1) {
            a += __shfl_xor_sync(~0u, a, o);
            b += __shfl_xor_sync(~0u, b, o);
        }
        if (lane == 0) { sP[h0*36 + c] = a*0.125f; sP[h1*36 + c] = b*0.125f; }
    }
    __syncwarp();
#pragma unroll
    for (int hh = 0; hh < 2; hh++) {
        int h = h0 + hh;
        float v = (lane < nv) ? sP[h*36 + lane] : -INFINITY;
        float mx = v;
        for (int o = 16; o; o >>= 1) mx = fmaxf(mx, __shfl_xor_sync(~0u, mx, o));
        float e = (lane < nv) ? __expf(v - mx) : 0.f;
        float sm = e;
        for (int o = 16; o; o >>= 1) sm += __shfl_xor_sync(~0u, sm, o);
        sP[h*36 + lane] = (nv > 0) ? e / sm : 0.f;
    }
    __syncwarp();
    float o00=0,o01=0,o10=0,o11=0;
    for (int c = 0; c < nv; c++) {
        float p0 = sP[h0*36 + c], p1 = sP[h1*36 + c];
        float v0 = sVC[c*65 + lane], v1 = sVC[c*65 + 32 + lane];
        o00 += p0*v0; o01 += p0*v1; o10 += p1*v0; o11 += p1*v1;
    }
    float gc0 = 1.f/(1.f + __expf(-g_gate[t*48 + h0*3]));
    float gc1 = 1.f/(1.f + __expf(-g_gate[t*48 + h1*3]));
    g_ocmp[qb + h0*64 + lane]      = o00*gc0;
    g_ocmp[qb + h0*64 + 32 + lane] = o01*gc0;
    g_ocmp[qb + h1*64 + lane]      = o10*gc1;
    g_ocmp[qb + h1*64 + 32 + lane] = o11*gc1;
    __syncthreads();

    // top-16 selection (warp 0, lane = candidate block)
    if (w == 0) {
        float imp = 0.f;
        for (int h = 0; h < 16; h++) imp += sP[h*36 + lane];
        int cur = t >> 6;
        float val;
        if (lane == 0 || lane == cur) val = 1e38f;       // forced
        else if (lane <= cur)         val = imp;          // candidate
        else                          val = -1e30f;       // NEG fill
        simp[lane] = val;
        __syncwarp();
        int rank = 0;
        for (int c = 0; c < 32; c++) {
            float vc = simp[c];
            if (vc > val || (vc == val && c < lane)) rank++;
        }
        unsigned msk = __ballot_sync(~0u, rank < NSEL);
        if (rank < NSEL) {
            int pos = __popc(msk & ((1u << lane) - 1));
            g_sel[t*NSEL + pos] = lane;
        }
    }
}

// ======================================================================
// Selected block-sparse attention. CTA/token, 128 thr, warp = 4 heads.
// Online softmax across 16 selected blocks of 64 keys.
// ======================================================================
__global__ __launch_bounds__(128) void sel_attn_kernel()
{
    int t = blockIdx.x;
    int tid = threadIdx.x, lane = tid & 31, w = tid >> 5;  // w: 0..3
    __shared__ float sK[64*68];
    __shared__ float sV[64*65];
    __shared__ float sQ[16*68];
    __shared__ float sPb[4][64*4];   // per-warp probs, packed [j][h]
    __shared__ int   sBlk[16];

    for (int i = tid; i < 1024; i += 128) {
        int h = i >> 6, d = i & 63;
        sQ[h*68 + d] = g_q[(size_t)t*1024 + i] * 0.125f;  // fold scale
    }
    if (tid < 16) sBlk[tid] = g_sel[t*16 + tid];

    const int h0 = w*4;
    float m[4] = {-INFINITY,-INFINITY,-INFINITY,-INFINITY};
    float l[4] = {0,0,0,0};
    float acc[4][2] = {};

    for (int bi = 0; bi < 16; bi++) {
        __syncthreads();
        int base = sBlk[bi] * 64;
        for (int i = tid; i < 4096; i += 128) {
            int j = i >> 6, d = i & 63;
            float kv = g_k[(size_t)(base + j)*64 + d];
            float vv = g_v[(size_t)(base + j)*64 + d];
            sK[j*68 + d] = kv;
            sV[j*65 + d] = vv;
        }
        __syncthreads();

        // scores: keys j0=lane, j1=lane+32, 4 heads
        float s[4][2] = {};
        for (int d4 = 0; d4 < 64; d4 += 4) {
            float4 k0 = *(float4*)&sK[lane*68 + d4];
            float4 k1 = *(float4*)&sK[(lane + 32)*68 + d4];
#pragma unroll
            for (int hh = 0; hh < 4; hh++) {
                float4 qv = *(float4*)&sQ[(h0 + hh)*68 + d4];
                s[hh][0] += qv.x*k0.x + qv.y*k0.y + qv.z*k0.z + qv.w*k0.w;
                s[hh][1] += qv.x*k1.x + qv.y*k1.y + qv.z*k1.z + qv.w*k1.w;
            }
        }
        bool ok0 = (base + lane)      <= t;
        bool ok1 = (base + lane + 32) <= t;
#pragma unroll
        for (int hh = 0; hh < 4; hh++) {
            float s0 = ok0 ? s[hh][0] : -INFINITY;
            float s1 = ok1 ? s[hh][1] : -INFINITY;
            float mb = fmaxf(s0, s1);
            for (int o = 16; o; o >>= 1) mb = fmaxf(mb, __shfl_xor_sync(~0u, mb, o));
            float mn = fmaxf(m[hh], mb);
            float corr = (mn == -INFINITY) ? 1.f : __expf(m[hh] - mn);
            float p0 = ok0 ? __expf(s0 - mn) : 0.f;
            float p1 = ok1 ? __expf(s1 - mn) : 0.f;
            float ls = p0 + p1;
            for (int o = 16; o; o >>= 1) ls += __shfl_xor_sync(~0u, ls, o);
            l[hh] = l[hh]*corr + ls;
            acc[hh][0] *= corr; acc[hh][1] *= corr;
            m[hh] = mn;
            sPb[w][lane*4 + hh]        = p0;
            sPb[w][(lane + 32)*4 + hh] = p1;
        }
        __syncwarp();
        for (int j = 0; j < 64; j++) {
            float4 p = *(float4*)&sPb[w][j*4];
            float v0 = sV[j*65 + lane];
            float v1 = sV[j*65 + 32 + lane];
            float pv[4] = {p.x, p.y, p.z, p.w};
#pragma unroll
            for (int hh = 0; hh < 4; hh++) {
                acc[hh][0] += pv[hh]*v0;
                acc[hh][1] += pv[hh]*v1;
            }
        }
        __syncwarp();
    }
#pragma unroll
    for (int hh = 0; hh < 4; hh++) {
        int h = h0 + hh;
        float gs = 1.f/(1.f + __expf(-g_gate[t*48 + h*3 + 1]));
        float inv = gs / l[hh];      // token t always visible -> l > 0
        size_t ob = (size_t)t*1024 + h*64 + lane;
        g_o[ob]      = acc[hh][0]*inv + g_ocmp[ob];
        g_o[ob + 32] = acc[hh][1]*inv + g_ocmp[ob + 32];
    }
}

// ======================================================================
extern "C" void kernel_launch(void* const* d_in, const int* in_sizes, int n_in,
                              void* d_out, int out_size)
{
    const float* x  = (const float*)d_in[0];
    const float* Wq = (const float*)d_in[1];
    const float* Wk = (const float*)d_in[2];
    const float* Wv = (const float*)d_in[3];
    const float* Wg = (const float*)d_in[4];
    const float* Wo = (const float*)d_in[5];
    float* out = (float*)d_out;

    proj_gemm_kernel<<<dim3(16, 16, 4), 256>>>(x, Wq, Wk, Wv, Wg);
    pool_kernel<<<32, 64>>>();
    cmp_attn_kernel<<<2048, 256>>>();
    sel_attn_kernel<<<2048, 128>>>();
    out_gemm_kernel<<<dim3(16, 16, 1), 256>>>(Wo, out);
}

// round 7
// speedup vs baseline: 1.2039x; 1.2039x over previous
#include <cuda_runtime.h>
#include <cuda_bf16.h>
#include <math.h>

// ---- constants ----
#define TT   2048
#define DM   1024
#define NH   16
#define HD   64
#define NBLK 32
#define NSEL 16

// ---- static scratch ----
__device__ float g_q   [TT * DM];
__device__ float g_k   [TT * HD];
__device__ float g_v   [TT * HD];
__device__ float g_gate[TT * 48];
__device__ float g_kc  [NBLK * HD];
__device__ float g_vc  [NBLK * HD];
__device__ float g_ocmp[TT * DM];
__device__ float g_o   [TT * DM];
__device__ int   g_sel [TT * NSEL];

// ======================================================================
// GEMM: C[M,N] = A[M,1024] * B[N,1024]^T.  BM=128 BN=64 BK=16, 256 thr.
// ======================================================================
__device__ __forceinline__ void gemm_body(const float* __restrict__ A,
                                          const float* __restrict__ B,
                                          float* __restrict__ C, int N)
{
    __shared__ float As[16][132];
    __shared__ float Bs[16][68];
    const int K = 1024;
    int tid = threadIdx.x;
    int tr = tid >> 4, tc = tid & 15;
    int row0 = blockIdx.y * 128, col0 = blockIdx.x * 64;
    float acc[8][4];
#pragma unroll
    for (int i = 0; i < 8; i++)
#pragma unroll
        for (int j = 0; j < 4; j++) acc[i][j] = 0.f;

    int ar = tid >> 2, aq = tid & 3;

    for (int kt = 0; kt < K; kt += 16) {
#pragma unroll
        for (int i = 0; i < 2; i++) {
            int r = ar + i * 64;
            float4 va = *(const float4*)(A + (size_t)(row0 + r) * K + kt + aq * 4);
            As[aq*4+0][r] = va.x; As[aq*4+1][r] = va.y;
            As[aq*4+2][r] = va.z; As[aq*4+3][r] = va.w;
        }
        {
            float4 vb = make_float4(0.f,0.f,0.f,0.f);
            if (col0 + ar < N)
                vb = *(const float4*)(B + (size_t)(col0 + ar) * K + kt + aq * 4);
            Bs[aq*4+0][ar] = vb.x; Bs[aq*4+1][ar] = vb.y;
            Bs[aq*4+2][ar] = vb.z; Bs[aq*4+3][ar] = vb.w;
        }
        __syncthreads();
#pragma unroll
        for (int k = 0; k < 16; k++) {
            float4 a0 = *(const float4*)(&As[k][tr*8]);
            float4 a1 = *(const float4*)(&As[k][tr*8+4]);
            float4 b  = *(const float4*)(&Bs[k][tc*4]);
            float av[8] = {a0.x,a0.y,a0.z,a0.w,a1.x,a1.y,a1.z,a1.w};
            float bv[4] = {b.x,b.y,b.z,b.w};
#pragma unroll
            for (int i = 0; i < 8; i++)
#pragma unroll
                for (int j = 0; j < 4; j++) acc[i][j] += av[i] * bv[j];
        }
        __syncthreads();
    }
    if (col0 + tc*4 < N) {
#pragma unroll
        for (int i = 0; i < 8; i++) {
            float4 o = make_float4(acc[i][0], acc[i][1], acc[i][2], acc[i][3]);
            *(float4*)(C + (size_t)(row0 + tr*8 + i) * N + col0 + tc*4) = o;
        }
    }
}

__global__ __launch_bounds__(256) void proj_gemm_kernel(
    const float* __restrict__ x,
    const float* __restrict__ Wq, const float* __restrict__ Wk,
    const float* __restrict__ Wv, const float* __restrict__ Wg)
{
    const float* B; float* C; int N;
    if      (blockIdx.z == 0) { B = Wq; C = g_q;    N = 1024; }
    else if (blockIdx.z == 1) { B = Wk; C = g_k;    N = 64;   }
    else if (blockIdx.z == 2) { B = Wv; C = g_v;    N = 64;   }
    else                      { B = Wg; C = g_gate; N = 48;   }
    if ((int)blockIdx.x * 64 >= N) return;
    gemm_body(x, B, C, N);
}

__global__ __launch_bounds__(256) void out_gemm_kernel(
    const float* __restrict__ Wo, float* __restrict__ out)
{
    gemm_body(g_o, Wo, out, 1024);
}

// ======================================================================
// Block mean pool
// ======================================================================
__global__ void pool_kernel()
{
    int b = blockIdx.x, d = threadIdx.x;
    float sk = 0.f, sv = 0.f;
    for (int j = 0; j < 64; j++) {
        sk += g_k[(b*64 + j)*64 + d];
        sv += g_v[(b*64 + j)*64 + d];
    }
    g_kc[b*64 + d] = sk * (1.f/64.f);
    g_vc[b*64 + d] = sv * (1.f/64.f);
}

// ======================================================================
// Compressed attention + top-k selection. CTA/token, 256 thr.
// ======================================================================
__global__ __launch_bounds__(256) void cmp_attn_kernel()
{
    int t = blockIdx.x;
    int tid = threadIdx.x, lane = tid & 31, w = tid >> 5;
    __shared__ float sKC[32*65], sVC[32*65];
    __shared__ float sP[16*36];
    __shared__ float simp[32];

    for (int i = tid; i < 2048; i += 256) {
        int c = i >> 6, d = i & 63;
        sKC[c*65 + d] = g_kc[i];
        sVC[c*65 + d] = g_vc[i];
    }
    __syncthreads();

    int nv = (t + 1) >> 6;
    int h0 = w*2, h1 = w*2 + 1;
    size_t qb = (size_t)t * 1024;
    float q00 = g_q[qb + h0*64 + lane],      q01 = g_q[qb + h0*64 + 32 + lane];
    float q10 = g_q[qb + h1*64 + lane],      q11 = g_q[qb + h1*64 + 32 + lane];

    for (int c = 0; c < nv; c++) {
        float k0 = sKC[c*65 + lane], k1 = sKC[c*65 + 32 + lane];
        float a = q00*k0 + q01*k1;
        float b = q10*k0 + q11*k1;
        for (int o = 16; o; o >>= 1) {
            a += __shfl_xor_sync(~0u, a, o);
            b += __shfl_xor_sync(~0u, b, o);
        }
        if (lane == 0) { sP[h0*36 + c] = a*0.125f; sP[h1*36 + c] = b*0.125f; }
    }
    __syncwarp();
#pragma unroll
    for (int hh = 0; hh < 2; hh++) {
        int h = h0 + hh;
        float v = (lane < nv) ? sP[h*36 + lane] : -INFINITY;
        float mx = v;
        for (int o = 16; o; o >>= 1) mx = fmaxf(mx, __shfl_xor_sync(~0u, mx, o));
        float e = (lane < nv) ? __expf(v - mx) : 0.f;
        float sm = e;
        for (int o = 16; o; o >>= 1) sm += __shfl_xor_sync(~0u, sm, o);
        sP[h*36 + lane] = (nv > 0) ? e / sm : 0.f;
    }
    __syncwarp();
    float o00=0,o01=0,o10=0,o11=0;
    for (int c = 0; c < nv; c++) {
        float p0 = sP[h0*36 + c], p1 = sP[h1*36 + c];
        float v0 = sVC[c*65 + lane], v1 = sVC[c*65 + 32 + lane];
        o00 += p0*v0; o01 += p0*v1; o10 += p1*v0; o11 += p1*v1;
    }
    float gc0 = 1.f/(1.f + __expf(-g_gate[t*48 + h0*3]));
    float gc1 = 1.f/(1.f + __expf(-g_gate[t*48 + h1*3]));
    g_ocmp[qb + h0*64 + lane]      = o00*gc0;
    g_ocmp[qb + h0*64 + 32 + lane] = o01*gc0;
    g_ocmp[qb + h1*64 + lane]      = o10*gc1;
    g_ocmp[qb + h1*64 + 32 + lane] = o11*gc1;
    __syncthreads();

    if (w == 0) {
        float imp = 0.f;
        for (int h = 0; h < 16; h++) imp += sP[h*36 + lane];
        int cur = t >> 6;
        float val;
        if (lane == 0 || lane == cur) val = 1e38f;
        else if (lane <= cur)         val = imp;
        else                          val = -1e30f;
        simp[lane] = val;
        __syncwarp();
        int rank = 0;
        for (int c = 0; c < 32; c++) {
            float vc = simp[c];
            if (vc > val || (vc == val && c < lane)) rank++;
        }
        unsigned msk = __ballot_sync(~0u, rank < NSEL);
        if (rank < NSEL) {
            int pos = __popc(msk & ((1u << lane) - 1));
            g_sel[t*NSEL + pos] = lane;
        }
    }
}

// ======================================================================
// tf32 MMA helpers (3xTF32 split for fp32-level accuracy)
// ======================================================================
__device__ __forceinline__ unsigned f2tf(float x) {
    unsigned r; asm("cvt.rna.tf32.f32 %0, %1;" : "=r"(r) : "f"(x)); return r;
}
__device__ __forceinline__ void tfsplit(float x, unsigned& h, unsigned& l) {
    h = f2tf(x);
    l = f2tf(x - __uint_as_float(h));
}
__device__ __forceinline__ void mma8(float* c, const unsigned* a, const unsigned* b) {
    asm("mma.sync.aligned.m16n8k8.row.col.f32.tf32.tf32.f32 "
        "{%0,%1,%2,%3}, {%4,%5,%6,%7}, {%8,%9}, {%0,%1,%2,%3};"
        : "+f"(c[0]), "+f"(c[1]), "+f"(c[2]), "+f"(c[3])
        : "r"(a[0]), "r"(a[1]), "r"(a[2]), "r"(a[3]), "r"(b[0]), "r"(b[1]));
}

// ======================================================================
// Selected block-sparse attention, tensor-core version.
// CTA = 1 token, 4 warps. Warp w handles keys [w*16, w*16+16) of each
// selected block; all 16 heads in one m16 tile. Shared online-softmax
// state (m,l identical across warps via smem exchanges). Per-warp O
// partials summed at the end.
// ======================================================================
__global__ __launch_bounds__(128) void sel_attn_kernel()
{
    __shared__ float sK[64*68];
    __shared__ float sV[64*72];      // reused as O-partial buffer after loop
    __shared__ float sQ[16*68];
    __shared__ float pbuf[4][16*20];
    __shared__ float sRmax[64], sRsum[64], sL[16];
    __shared__ int   sBlk[16];

    int t = blockIdx.x;
    int tid = threadIdx.x, lane = tid & 31, w = tid >> 5;
    int r4 = lane >> 2, q4 = lane & 3;

    for (int i = tid; i < 1024; i += 128)
        sQ[(i>>6)*68 + (i&63)] = g_q[(size_t)t*1024 + i] * 0.125f;
    if (tid < 16) sBlk[tid] = g_sel[t*16 + tid];
    __syncthreads();

    // Q A-fragments (m16 k8 row-major), hi/lo split, held in registers
    unsigned qh[32], ql[32];
#pragma unroll
    for (int kt = 0; kt < 8; kt++) {
        float a0 = sQ[r4*68 + kt*8 + q4];
        float a1 = sQ[(r4+8)*68 + kt*8 + q4];
        float a2 = sQ[r4*68 + kt*8 + q4 + 4];
        float a3 = sQ[(r4+8)*68 + kt*8 + q4 + 4];
        tfsplit(a0, qh[kt*4+0], ql[kt*4+0]);
        tfsplit(a1, qh[kt*4+1], ql[kt*4+1]);
        tfsplit(a2, qh[kt*4+2], ql[kt*4+2]);
        tfsplit(a3, qh[kt*4+3], ql[kt*4+3]);
    }

    float o[32];
#pragma unroll
    for (int i = 0; i < 32; i++) o[i] = 0.f;
    float m0 = -INFINITY, m1 = -INFINITY, l0 = 0.f, l1 = 0.f;
    float* pb = pbuf[w];

    for (int bi = 0; bi < 16; bi++) {
        __syncthreads();
        int base = sBlk[bi] * 64;
        for (int i = tid; i < 1024; i += 128) {
            int j = i >> 4, d4 = (i & 15) * 4;
            float4 kv = *(const float4*)&g_k[(size_t)(base + j)*64 + d4];
            float4 vv = *(const float4*)&g_v[(size_t)(base + j)*64 + d4];
            *(float4*)&sK[j*68 + d4] = kv;
            *(float4*)&sV[j*72 + d4] = vv;
        }
        __syncthreads();

        // ---- S[16 heads x 16 keys] = Q K^T (3xTF32) ----
        float c0[4] = {0,0,0,0}, c1[4] = {0,0,0,0};
#pragma unroll
        for (int kt = 0; kt < 8; kt++) {
#pragma unroll
            for (int nt = 0; nt < 2; nt++) {
                int key = w*16 + nt*8 + r4;
                float b0f = sK[key*68 + kt*8 + q4];
                float b1f = sK[key*68 + kt*8 + q4 + 4];
                unsigned bh[2], bl[2];
                tfsplit(b0f, bh[0], bl[0]);
                tfsplit(b1f, bh[1], bl[1]);
                float* cc = nt ? c1 : c0;
                mma8(cc, &qh[kt*4], bh);
                mma8(cc, &qh[kt*4], bl);
                mma8(cc, &ql[kt*4], bh);
            }
        }
        // causal mask (key index depends only on columns)
        int k0g = base + w*16 + 2*q4;
        if (k0g     > t) { c0[0] = -1e30f; c0[2] = -1e30f; }
        if (k0g + 1 > t) { c0[1] = -1e30f; c0[3] = -1e30f; }
        if (k0g + 8 > t) { c1[0] = -1e30f; c1[2] = -1e30f; }
        if (k0g + 9 > t) { c1[1] = -1e30f; c1[3] = -1e30f; }

        // warp-local row max over this warp's 16 keys
        float lm0 = fmaxf(fmaxf(c0[0], c0[1]), fmaxf(c1[0], c1[1]));
        float lm1 = fmaxf(fmaxf(c0[2], c0[3]), fmaxf(c1[2], c1[3]));
        lm0 = fmaxf(lm0, __shfl_xor_sync(~0u, lm0, 1));
        lm0 = fmaxf(lm0, __shfl_xor_sync(~0u, lm0, 2));
        lm1 = fmaxf(lm1, __shfl_xor_sync(~0u, lm1, 1));
        lm1 = fmaxf(lm1, __shfl_xor_sync(~0u, lm1, 2));
        if (q4 == 0) { sRmax[w*16 + r4] = lm0; sRmax[w*16 + r4 + 8] = lm1; }
        __syncthreads();
        float gm0 = fmaxf(fmaxf(sRmax[r4],    sRmax[16+r4]), fmaxf(sRmax[32+r4], sRmax[48+r4]));
        float gm1 = fmaxf(fmaxf(sRmax[8+r4],  sRmax[24+r4]), fmaxf(sRmax[40+r4], sRmax[56+r4]));
        float mn0 = fmaxf(m0, gm0), mn1 = fmaxf(m1, gm1);
        float corr0 = __expf(m0 - mn0), corr1 = __expf(m1 - mn1);
        float p00 = __expf(c0[0]-mn0), p01 = __expf(c0[1]-mn0);
        float p02 = __expf(c0[2]-mn1), p03 = __expf(c0[3]-mn1);
        float p10 = __expf(c1[0]-mn0), p11 = __expf(c1[1]-mn0);
        float p12 = __expf(c1[2]-mn1), p13 = __expf(c1[3]-mn1);
        pb[r4*20 + 2*q4]           = p00; pb[r4*20 + 2*q4 + 1]         = p01;
        pb[(r4+8)*20 + 2*q4]       = p02; pb[(r4+8)*20 + 2*q4 + 1]     = p03;
        pb[r4*20 + 8 + 2*q4]       = p10; pb[r4*20 + 8 + 2*q4 + 1]     = p11;
        pb[(r4+8)*20 + 8 + 2*q4]   = p12; pb[(r4+8)*20 + 8 + 2*q4 + 1] = p13;
        float ls0 = p00 + p01 + p10 + p11;
        float ls1 = p02 + p03 + p12 + p13;
        ls0 += __shfl_xor_sync(~0u, ls0, 1); ls0 += __shfl_xor_sync(~0u, ls0, 2);
        ls1 += __shfl_xor_sync(~0u, ls1, 1); ls1 += __shfl_xor_sync(~0u, ls1, 2);
        if (q4 == 0) { sRsum[w*16 + r4] = ls0; sRsum[w*16 + r4 + 8] = ls1; }
#pragma unroll
        for (int nt = 0; nt < 8; nt++) {
            o[nt*4+0] *= corr0; o[nt*4+1] *= corr0;
            o[nt*4+2] *= corr1; o[nt*4+3] *= corr1;
        }
        m0 = mn0; m1 = mn1;
        l0 *= corr0; l1 *= corr1;
        __syncthreads();
        l0 += sRsum[r4]   + sRsum[16+r4] + sRsum[32+r4] + sRsum[48+r4];
        l1 += sRsum[8+r4] + sRsum[24+r4] + sRsum[40+r4] + sRsum[56+r4];

        // ---- O[16 x 64] += P[16 x 16] V[16 x 64] (3xTF32) ----
#pragma unroll
        for (int kt = 0; kt < 2; kt++) {
            unsigned ah[4], al[4];
            tfsplit(pb[r4*20 + kt*8 + q4],          ah[0], al[0]);
            tfsplit(pb[(r4+8)*20 + kt*8 + q4],      ah[1], al[1]);
            tfsplit(pb[r4*20 + kt*8 + q4 + 4],      ah[2], al[2]);
            tfsplit(pb[(r4+8)*20 + kt*8 + q4 + 4],  ah[3], al[3]);
#pragma unroll
            for (int nt = 0; nt < 8; nt++) {
                float b0f = sV[(w*16 + kt*8 + q4)*72     + nt*8 + r4];
                float b1f = sV[(w*16 + kt*8 + q4 + 4)*72 + nt*8 + r4];
                unsigned bh[2], bl[2];
                tfsplit(b0f, bh[0], bl[0]);
                tfsplit(b1f, bh[1], bl[1]);
                mma8(&o[nt*4], ah, bh);
                mma8(&o[nt*4], ah, bl);
                mma8(&o[nt*4], al, bh);
            }
        }
    }

    __syncthreads();
    // dump per-warp O partials into sV (reused): rows w*16 + headrow
#pragma unroll
    for (int nt = 0; nt < 8; nt++) {
        *(float2*)&sV[(w*16 + r4)*72   + nt*8 + 2*q4] = make_float2(o[nt*4+0], o[nt*4+1]);
        *(float2*)&sV[(w*16 + r4+8)*72 + nt*8 + 2*q4] = make_float2(o[nt*4+2], o[nt*4+3]);
    }
    if (w == 0 && q4 == 0) { sL[r4] = l0; sL[r4+8] = l1; }
    __syncthreads();
    for (int i = tid; i < 1024; i += 128) {
        int h = i >> 6, d = i & 63;
        float s = sV[h*72 + d] + sV[(16+h)*72 + d] + sV[(32+h)*72 + d] + sV[(48+h)*72 + d];
        float gs = 1.f/(1.f + __expf(-g_gate[t*48 + h*3 + 1]));
        size_t ob = (size_t)t*1024 + i;
        g_o[ob] = s * gs / sL[h] + g_ocmp[ob];
    }
}

// ======================================================================
extern "C" void kernel_launch(void* const* d_in, const int* in_sizes, int n_in,
                              void* d_out, int out_size)
{
    const float* x  = (const float*)d_in[0];
    const float* Wq = (const float*)d_in[1];
    const float* Wk = (const float*)d_in[2];
    const float* Wv = (const float*)d_in[3];
    const float* Wg = (const float*)d_in[4];
    const float* Wo = (const float*)d_in[5];
    float* out = (float*)d_out;

    proj_gemm_kernel<<<dim3(16, 16, 4), 256>>>(x, Wq, Wk, Wv, Wg);
    pool_kernel<<<32, 64>>>();
    cmp_attn_kernel<<<2048, 256>>>();
    sel_attn_kernel<<<2048, 128>>>();
    out_gemm_kernel<<<dim3(16, 16, 1), 256>>>(Wo, out);
}

// round 8
// speedup vs baseline: 1.2879x; 1.0698x over previous
#include <cuda_runtime.h>
#include <cuda_bf16.h>
#include <math.h>

// ---- constants ----
#define TT   2048
#define DM   1024
#define NH   16
#define HD   64
#define NBLK 32
#define NSEL 16

// ---- static scratch ----
__device__ float g_q   [TT * DM];
__device__ float g_k   [TT * HD];
__device__ float g_v   [TT * HD];
__device__ float g_gate[TT * 48];
__device__ float g_kc  [NBLK * HD];
__device__ float g_vc  [NBLK * HD];
__device__ float g_ocmp[TT * DM];
__device__ float g_o   [TT * DM];
__device__ int   g_sel [TT * NSEL];
// pre-split K/V (bf16 hi/lo); V stored transposed [d][t]
__device__ __nv_bfloat16 g_kh[TT * HD];
__device__ __nv_bfloat16 g_kl[TT * HD];
__device__ __nv_bfloat16 g_vhT[HD * TT];
__device__ __nv_bfloat16 g_vlT[HD * TT];

// ======================================================================
// GEMM: C[M,N] = A[M,1024] * B[N,1024]^T.  BM=128 BN=64 BK=16, 256 thr.
// ======================================================================
__device__ __forceinline__ void gemm_body(const float* __restrict__ A,
                                          const float* __restrict__ B,
                                          float* __restrict__ C, int N)
{
    __shared__ float As[16][132];
    __shared__ float Bs[16][68];
    const int K = 1024;
    int tid = threadIdx.x;
    int tr = tid >> 4, tc = tid & 15;
    int row0 = blockIdx.y * 128, col0 = blockIdx.x * 64;
    float acc[8][4];
#pragma unroll
    for (int i = 0; i < 8; i++)
#pragma unroll
        for (int j = 0; j < 4; j++) acc[i][j] = 0.f;

    int ar = tid >> 2, aq = tid & 3;

    for (int kt = 0; kt < K; kt += 16) {
#pragma unroll
        for (int i = 0; i < 2; i++) {
            int r = ar + i * 64;
            float4 va = *(const float4*)(A + (size_t)(row0 + r) * K + kt + aq * 4);
            As[aq*4+0][r] = va.x; As[aq*4+1][r] = va.y;
            As[aq*4+2][r] = va.z; As[aq*4+3][r] = va.w;
        }
        {
            float4 vb = make_float4(0.f,0.f,0.f,0.f);
            if (col0 + ar < N)
                vb = *(const float4*)(B + (size_t)(col0 + ar) * K + kt + aq * 4);
            Bs[aq*4+0][ar] = vb.x; Bs[aq*4+1][ar] = vb.y;
            Bs[aq*4+2][ar] = vb.z; Bs[aq*4+3][ar] = vb.w;
        }
        __syncthreads();
#pragma unroll
        for (int k = 0; k < 16; k++) {
            float4 a0 = *(const float4*)(&As[k][tr*8]);
            float4 a1 = *(const float4*)(&As[k][tr*8+4]);
            float4 b  = *(const float4*)(&Bs[k][tc*4]);
            float av[8] = {a0.x,a0.y,a0.z,a0.w,a1.x,a1.y,a1.z,a1.w};
            float bv[4] = {b.x,b.y,b.z,b.w};
#pragma unroll
            for (int i = 0; i < 8; i++)
#pragma unroll
                for (int j = 0; j < 4; j++) acc[i][j] += av[i] * bv[j];
        }
        __syncthreads();
    }
    if (col0 + tc*4 < N) {
#pragma unroll
        for (int i = 0; i < 8; i++) {
            float4 o = make_float4(acc[i][0], acc[i][1], acc[i][2], acc[i][3]);
            *(float4*)(C + (size_t)(row0 + tr*8 + i) * N + col0 + tc*4) = o;
        }
    }
}

__global__ __launch_bounds__(256) void proj_gemm_kernel(
    const float* __restrict__ x,
    const float* __restrict__ Wq, const float* __restrict__ Wk,
    const float* __restrict__ Wv, const float* __restrict__ Wg)
{
    const float* B; float* C; int N;
    if      (blockIdx.z == 0) { B = Wq; C = g_q;    N = 1024; }
    else if (blockIdx.z == 1) { B = Wk; C = g_k;    N = 64;   }
    else if (blockIdx.z == 2) { B = Wv; C = g_v;    N = 64;   }
    else                      { B = Wg; C = g_gate; N = 48;   }
    if ((int)blockIdx.x * 64 >= N) return;
    gemm_body(x, B, C, N);
}

__global__ __launch_bounds__(256) void out_gemm_kernel(
    const float* __restrict__ Wo, float* __restrict__ out)
{
    gemm_body(g_o, Wo, out, 1024);
}

// ======================================================================
// Block mean pool
// ======================================================================
__global__ void pool_kernel()
{
    int b = blockIdx.x, d = threadIdx.x;
    float sk = 0.f, sv = 0.f;
    for (int j = 0; j < 64; j++) {
        sk += g_k[(b*64 + j)*64 + d];
        sv += g_v[(b*64 + j)*64 + d];
    }
    g_kc[b*64 + d] = sk * (1.f/64.f);
    g_vc[b*64 + d] = sv * (1.f/64.f);
}

// ======================================================================
// Pre-split K/V into bf16 hi/lo (V transposed)
// ======================================================================
__global__ __launch_bounds__(256) void split_kv_kernel()
{
    int i = blockIdx.x * 256 + threadIdx.x;   // 131072 total
    int t = i >> 6, d = i & 63;
    float k = g_k[i], v = g_v[i];
    __nv_bfloat16 kh = __float2bfloat16(k);
    __nv_bfloat16 kl = __float2bfloat16(k - __bfloat162float(kh));
    g_kh[i] = kh; g_kl[i] = kl;
    __nv_bfloat16 vh = __float2bfloat16(v);
    __nv_bfloat16 vl = __float2bfloat16(v - __bfloat162float(vh));
    g_vhT[d * TT + t] = vh; g_vlT[d * TT + t] = vl;
}

// ======================================================================
// Compressed attention + top-k selection. CTA/token, 256 thr.
// ======================================================================
__global__ __launch_bounds__(256) void cmp_attn_kernel()
{
    int t = blockIdx.x;
    int tid = threadIdx.x, lane = tid & 31, w = tid >> 5;
    __shared__ float sKC[32*65], sVC[32*65];
    __shared__ float sP[16*36];
    __shared__ float simp[32];

    for (int i = tid; i < 2048; i += 256) {
        int c = i >> 6, d = i & 63;
        sKC[c*65 + d] = g_kc[i];
        sVC[c*65 + d] = g_vc[i];
    }
    __syncthreads();

    int nv = (t + 1) >> 6;
    int h0 = w*2, h1 = w*2 + 1;
    size_t qb = (size_t)t * 1024;
    float q00 = g_q[qb + h0*64 + lane],      q01 = g_q[qb + h0*64 + 32 + lane];
    float q10 = g_q[qb + h1*64 + lane],      q11 = g_q[qb + h1*64 + 32 + lane];

    for (int c = 0; c < nv; c++) {
        float k0 = sKC[c*65 + lane], k1 = sKC[c*65 + 32 + lane];
        float a = q00*k0 + q01*k1;
        float b = q10*k0 + q11*k1;
        for (int o = 16; o; o >>= 1) {
            a += __shfl_xor_sync(~0u, a, o);
            b += __shfl_xor_sync(~0u, b, o);
        }
        if (lane == 0) { sP[h0*36 + c] = a*0.125f; sP[h1*36 + c] = b*0.125f; }
    }
    __syncwarp();
#pragma unroll
    for (int hh = 0; hh < 2; hh++) {
        int h = h0 + hh;
        float v = (lane < nv) ? sP[h*36 + lane] : -INFINITY;
        float mx = v;
        for (int o = 16; o; o >>= 1) mx = fmaxf(mx, __shfl_xor_sync(~0u, mx, o));
        float e = (lane < nv) ? __expf(v - mx) : 0.f;
        float sm = e;
        for (int o = 16; o; o >>= 1) sm += __shfl_xor_sync(~0u, sm, o);
        sP[h*36 + lane] = (nv > 0) ? e / sm : 0.f;
    }
    __syncwarp();
    float o00=0,o01=0,o10=0,o11=0;
    for (int c = 0; c < nv; c++) {
        float p0 = sP[h0*36 + c], p1 = sP[h1*36 + c];
        float v0 = sVC[c*65 + lane], v1 = sVC[c*65 + 32 + lane];
        o00 += p0*v0; o01 += p0*v1; o10 += p1*v0; o11 += p1*v1;
    }
    float gc0 = 1.f/(1.f + __expf(-g_gate[t*48 + h0*3]));
    float gc1 = 1.f/(1.f + __expf(-g_gate[t*48 + h1*3]));
    g_ocmp[qb + h0*64 + lane]      = o00*gc0;
    g_ocmp[qb + h0*64 + 32 + lane] = o01*gc0;
    g_ocmp[qb + h1*64 + lane]      = o10*gc1;
    g_ocmp[qb + h1*64 + 32 + lane] = o11*gc1;
    __syncthreads();

    if (w == 0) {
        float imp = 0.f;
        for (int h = 0; h < 16; h++) imp += sP[h*36 + lane];
        int cur = t >> 6;
        float val;
        if (lane == 0 || lane == cur) val = 1e38f;
        else if (lane <= cur)         val = imp;
        else                          val = -1e30f;
        simp[lane] = val;
        __syncwarp();
        int rank = 0;
        for (int c = 0; c < 32; c++) {
            float vc = simp[c];
            if (vc > val || (vc == val && c < lane)) rank++;
        }
        unsigned msk = __ballot_sync(~0u, rank < NSEL);
        if (rank < NSEL) {
            int pos = __popc(msk & ((1u << lane) - 1));
            g_sel[t*NSEL + pos] = lane;
        }
    }
}

// ======================================================================
// bf16 helpers
// ======================================================================
__device__ __forceinline__ void bfsplit2(float x0, float x1, unsigned& h, unsigned& l)
{
    __nv_bfloat162 hh = __floats2bfloat162_rn(x0, x1);
    float r0 = x0 - __bfloat162float(hh.x);
    float r1 = x1 - __bfloat162float(hh.y);
    __nv_bfloat162 ll = __floats2bfloat162_rn(r0, r1);
    h = *(unsigned*)&hh; l = *(unsigned*)&ll;
}
__device__ __forceinline__ void mma16(float* c, const unsigned* a, unsigned b0, unsigned b1)
{
    asm("mma.sync.aligned.m16n8k16.row.col.f32.bf16.bf16.f32 "
        "{%0,%1,%2,%3}, {%4,%5,%6,%7}, {%8,%9}, {%0,%1,%2,%3};"
        : "+f"(c[0]), "+f"(c[1]), "+f"(c[2]), "+f"(c[3])
        : "r"(a[0]), "r"(a[1]), "r"(a[2]), "r"(a[3]), "r"(b0), "r"(b1));
}

// ======================================================================
// Selected block-sparse attention (bf16x2, per-warp online softmax).
// CTA = 1 token, 4 warps; warp w owns keys [w*16, w*16+16) of each block.
// ======================================================================
#define KP 72   // tile pitch in bf16 halfwords
__global__ __launch_bounds__(128) void sel_attn_kernel()
{
    __shared__ __align__(16) unsigned char sraw[36864];
    __shared__ float sQ[16*68];
    __shared__ unsigned pbuf[4][2][16*12];
    __shared__ int sBlk[16];

    __nv_bfloat16* sKH = (__nv_bfloat16*)(sraw);
    __nv_bfloat16* sKL = (__nv_bfloat16*)(sraw +  9216);
    __nv_bfloat16* sVH = (__nv_bfloat16*)(sraw + 18432);  // [d][key]
    __nv_bfloat16* sVL = (__nv_bfloat16*)(sraw + 27648);

    int t = blockIdx.x;
    int tid = threadIdx.x, lane = tid & 31, w = tid >> 5;
    int r4 = lane >> 2, q4 = lane & 3;

    for (int i = tid; i < 1024; i += 128)
        sQ[(i>>6)*68 + (i&63)] = g_q[(size_t)t*1024 + i] * 0.125f;
    if (tid < 16) sBlk[tid] = g_sel[t*16 + tid];
    __syncthreads();

    // Q A-fragments (m16k16), bf16 hi/lo, registers
    unsigned qh[16], ql[16];
#pragma unroll
    for (int kt = 0; kt < 4; kt++) {
        int k0 = kt*16 + 2*q4;
        bfsplit2(sQ[r4*68+k0],       sQ[r4*68+k0+1],       qh[kt*4+0], ql[kt*4+0]);
        bfsplit2(sQ[(r4+8)*68+k0],   sQ[(r4+8)*68+k0+1],   qh[kt*4+1], ql[kt*4+1]);
        bfsplit2(sQ[r4*68+k0+8],     sQ[r4*68+k0+9],       qh[kt*4+2], ql[kt*4+2]);
        bfsplit2(sQ[(r4+8)*68+k0+8], sQ[(r4+8)*68+k0+9],   qh[kt*4+3], ql[kt*4+3]);
    }

    float o[32];
#pragma unroll
    for (int i = 0; i < 32; i++) o[i] = 0.f;
    float m0 = -INFINITY, m1 = -INFINITY, l0 = 0.f, l1 = 0.f;

    for (int bi = 0; bi < 16; bi++) {
        __syncthreads();
        int base = sBlk[bi] * 64;
        // stage K (natural) and V (transposed), hi+lo
        for (int i = tid; i < 512; i += 128) {
            int key = i >> 3, d8 = (i & 7) * 8;
            *(uint4*)&sKH[key*KP + d8] = *(const uint4*)&g_kh[(size_t)(base+key)*64 + d8];
            *(uint4*)&sKL[key*KP + d8] = *(const uint4*)&g_kl[(size_t)(base+key)*64 + d8];
        }
        for (int i = tid; i < 512; i += 128) {
            int d = i >> 3, k8 = (i & 7) * 8;
            *(uint4*)&sVH[d*KP + k8] = *(const uint4*)&g_vhT[(size_t)d*TT + base + k8];
            *(uint4*)&sVL[d*KP + k8] = *(const uint4*)&g_vlT[(size_t)d*TT + base + k8];
        }
        __syncthreads();

        // ---- S[16h x 16k] = Q K^T ----
        float c[2][4] = {{0,0,0,0},{0,0,0,0}};
#pragma unroll
        for (int kt = 0; kt < 4; kt++) {
#pragma unroll
            for (int nt = 0; nt < 2; nt++) {
                int key = w*16 + nt*8 + r4;
                const __nv_bfloat16* kb = &sKH[key*KP + kt*16 + 2*q4];
                unsigned bh0 = *(const unsigned*)kb;
                unsigned bh1 = *(const unsigned*)(kb + 8);
                const __nv_bfloat16* kl_ = &sKL[key*KP + kt*16 + 2*q4];
                unsigned bl0 = *(const unsigned*)kl_;
                unsigned bl1 = *(const unsigned*)(kl_ + 8);
                mma16(c[nt], &qh[kt*4], bh0, bh1);
                mma16(c[nt], &qh[kt*4], bl0, bl1);
                mma16(c[nt], &ql[kt*4], bh0, bh1);
            }
        }
        // causal mask: col = nt*8 + 2*q4 (+1)
#pragma unroll
        for (int nt = 0; nt < 2; nt++) {
            int kg = base + w*16 + nt*8 + 2*q4;
            if (kg     > t) { c[nt][0] = -1e30f; c[nt][2] = -1e30f; }
            if (kg + 1 > t) { c[nt][1] = -1e30f; c[nt][3] = -1e30f; }
        }

        // per-warp online softmax (rows r4 -> m0, r4+8 -> m1)
        float lm0 = fmaxf(fmaxf(c[0][0], c[0][1]), fmaxf(c[1][0], c[1][1]));
        float lm1 = fmaxf(fmaxf(c[0][2], c[0][3]), fmaxf(c[1][2], c[1][3]));
        lm0 = fmaxf(lm0, __shfl_xor_sync(~0u, lm0, 1));
        lm0 = fmaxf(lm0, __shfl_xor_sync(~0u, lm0, 2));
        lm1 = fmaxf(lm1, __shfl_xor_sync(~0u, lm1, 1));
        lm1 = fmaxf(lm1, __shfl_xor_sync(~0u, lm1, 2));
        float mn0 = fmaxf(m0, lm0), mn1 = fmaxf(m1, lm1);
        float corr0 = __expf(m0 - mn0), corr1 = __expf(m1 - mn1);
        float p[2][4];
#pragma unroll
        for (int nt = 0; nt < 2; nt++) {
            p[nt][0] = __expf(c[nt][0] - mn0);
            p[nt][1] = __expf(c[nt][1] - mn0);
            p[nt][2] = __expf(c[nt][2] - mn1);
            p[nt][3] = __expf(c[nt][3] - mn1);
        }
        float ls0 = p[0][0] + p[0][1] + p[1][0] + p[1][1];
        float ls1 = p[0][2] + p[0][3] + p[1][2] + p[1][3];
        ls0 += __shfl_xor_sync(~0u, ls0, 1); ls0 += __shfl_xor_sync(~0u, ls0, 2);
        ls1 += __shfl_xor_sync(~0u, ls1, 1); ls1 += __shfl_xor_sync(~0u, ls1, 2);
        l0 = l0*corr0 + ls0;
        l1 = l1*corr1 + ls1;
#pragma unroll
        for (int nt = 0; nt < 8; nt++) {
            o[nt*4+0] *= corr0; o[nt*4+1] *= corr0;
            o[nt*4+2] *= corr1; o[nt*4+3] *= corr1;
        }
        m0 = mn0; m1 = mn1;

        // store P (bf16 hi/lo pairs)
#pragma unroll
        for (int nt = 0; nt < 2; nt++) {
            unsigned ph, pl;
            bfsplit2(p[nt][0], p[nt][1], ph, pl);
            pbuf[w][0][r4*12 + nt*4 + q4] = ph;
            pbuf[w][1][r4*12 + nt*4 + q4] = pl;
            bfsplit2(p[nt][2], p[nt][3], ph, pl);
            pbuf[w][0][(r4+8)*12 + nt*4 + q4] = ph;
            pbuf[w][1][(r4+8)*12 + nt*4 + q4] = pl;
        }
        __syncwarp();

        // ---- O[16h x 64d] += P[16 x 16] V[16 x 64] ----
        unsigned ah[4] = { pbuf[w][0][r4*12 + q4],     pbuf[w][0][(r4+8)*12 + q4],
                           pbuf[w][0][r4*12 + q4 + 4], pbuf[w][0][(r4+8)*12 + q4 + 4] };
        unsigned al[4] = { pbuf[w][1][r4*12 + q4],     pbuf[w][1][(r4+8)*12 + q4],
                           pbuf[w][1][r4*12 + q4 + 4], pbuf[w][1][(r4+8)*12 + q4 + 4] };
#pragma unroll
        for (int nt = 0; nt < 8; nt++) {
            int d = nt*8 + r4;
            const __nv_bfloat16* vb = &sVH[d*KP + w*16 + 2*q4];
            unsigned bh0 = *(const unsigned*)vb;
            unsigned bh1 = *(const unsigned*)(vb + 8);
            const __nv_bfloat16* vl_ = &sVL[d*KP + w*16 + 2*q4];
            unsigned bl0 = *(const unsigned*)vl_;
            unsigned bl1 = *(const unsigned*)(vl_ + 8);
            mma16(&o[nt*4], ah, bh0, bh1);
            mma16(&o[nt*4], ah, bl0, bl1);
            mma16(&o[nt*4], al, bh0, bh1);
        }
        __syncwarp();
    }

    // ---- merge 4 per-warp partials ----
    __syncthreads();
    float* mo = (float*)sraw;                 // [w][16][66]
    float* ml = (float*)(sraw + 16896);       // [w][16][2] (m,l)
#pragma unroll
    for (int nt = 0; nt < 8; nt++) {
        *(float2*)&mo[(w*16 + r4)*66   + nt*8 + 2*q4] = make_float2(o[nt*4+0], o[nt*4+1]);
        *(float2*)&mo[(w*16 + r4+8)*66 + nt*8 + 2*q4] = make_float2(o[nt*4+2], o[nt*4+3]);
    }
    if (q4 == 0) {
        ml[w*32 + r4*2]       = m0; ml[w*32 + r4*2 + 1]       = l0;
        ml[w*32 + (r4+8)*2]   = m1; ml[w*32 + (r4+8)*2 + 1]   = l1;
    }
    __syncthreads();
    for (int i = tid; i < 1024; i += 128) {
        int h = i >> 6, d = i & 63;
        float ms = fmaxf(fmaxf(ml[h*2], ml[32 + h*2]),
                         fmaxf(ml[64 + h*2], ml[96 + h*2]));
        float li = 0.f, oi = 0.f;
#pragma unroll
        for (int ww = 0; ww < 4; ww++) {
            float ew = __expf(ml[ww*32 + h*2] - ms);
            li += ml[ww*32 + h*2 + 1] * ew;
            oi += mo[(ww*16 + h)*66 + d] * ew;
        }
        float gs = 1.f/(1.f + __expf(-g_gate[t*48 + h*3 + 1]));
        size_t ob = (size_t)t*1024 + i;
        g_o[ob] = oi * gs / li + g_ocmp[ob];
    }
}

// ======================================================================
extern "C" void kernel_launch(void* const* d_in, const int* in_sizes, int n_in,
                              void* d_out, int out_size)
{
    const float* x  = (const float*)d_in[0];
    const float* Wq = (const float*)d_in[1];
    const float* Wk = (const float*)d_in[2];
    const float* Wv = (const float*)d_in[3];
    const float* Wg = (const float*)d_in[4];
    const float* Wo = (const float*)d_in[5];
    float* out = (float*)d_out;

    proj_gemm_kernel<<<dim3(16, 16, 4), 256>>>(x, Wq, Wk, Wv, Wg);
    pool_kernel<<<32, 64>>>();
    split_kv_kernel<<<512, 256>>>();
    cmp_attn_kernel<<<2048, 256>>>();
    sel_attn_kernel<<<2048, 128>>>();
    out_gemm_kernel<<<dim3(16, 16, 1), 256>>>(Wo, out);
}